// round 3
// baseline (speedup 1.0000x reference)
#include <cuda_runtime.h>

#define BATCH 8
#define NPTS  2048
#define KNN   16
#define TPB   32
#define TILES (NPTS / TPB)      // 64
#define NCB   (2 * BATCH)       // 16 (cloud,batch) groups

// Sorted point sets (by x) and per-tile partial sums.
__device__ float4 g_sorted[NCB * NPTS];       // 512 KB
__device__ float  g_partials[NCB * TILES];    // 1024 floats

// ---------------- sort: bitonic per (cloud,batch), key = x ----------------
__global__ __launch_bounds__(1024)
void sort_kernel(const float* __restrict__ seed, const float* __restrict__ gts) {
    __shared__ float4 s[NPTS];                 // 32 KB
    const int b = blockIdx.x, c = blockIdx.y;
    const int tid = threadIdx.x;
    const float* __restrict__ src = (c == 0 ? seed : gts) + (size_t)b * NPTS * 3;

    for (int i = tid; i < NPTS; i += 1024)
        s[i] = make_float4(src[3*i+0], src[3*i+1], src[3*i+2], 0.0f);

    for (int k = 2; k <= NPTS; k <<= 1) {
        for (int j = k >> 1; j > 0; j >>= 1) {
            __syncthreads();
            const int i = ((tid & ~(j - 1)) << 1) | (tid & (j - 1));
            const int q = i | j;
            const float4 a  = s[i];
            const float4 bb = s[q];
            const bool up = (i & k) == 0;
            if ((a.x > bb.x) == up) { s[i] = bb; s[q] = a; }
        }
    }
    __syncthreads();

    float4* __restrict__ dst = g_sorted + (c * BATCH + b) * NPTS;
    for (int i = tid; i < NPTS; i += 1024) dst[i] = s[i];
}

// ---------------- knn: one warp per 32 consecutive sorted points ----------------
// Parallel (depth-2) sorted-ascending insert; guarded (rare after warmup).
#define INSERT(dv) do {                                                   \
    if ((dv) < r[KNN-1]) {                                                \
        _Pragma("unroll")                                                 \
        for (int k = KNN-1; k >= 1; --k)                                  \
            r[k] = fminf(r[k], fmaxf(r[k-1], (dv)));                      \
        r[0] = fminf(r[0], (dv));                                         \
    } } while (0)

#define DIST(q) fmaf((q).x - pi.x, (q).x - pi.x,                          \
                fmaf((q).y - pi.y, (q).y - pi.y,                          \
                     ((q).z - pi.z) * ((q).z - pi.z)))

__global__ __launch_bounds__(TPB)
void knn_kernel() {
    const int tile = blockIdx.x, b = blockIdx.y, c = blockIdx.z;
    const int lane = threadIdx.x;
    const float4* __restrict__ ps = g_sorted + (c * BATCH + b) * NPTS;

    const int   p  = tile * TPB + lane;
    const float4 pi = ps[p];

    float r[KNN];
#pragma unroll
    for (int k = 0; k < KNN; k++) r[k] = 3.0e38f;

    // Warp-uniform scan center: broadcast loads (same addr across lanes).
    const int j0 = tile * TPB + (TPB / 2);

    { // s = 0
        const float4 q = ps[j0];
        const float d = DIST(q);
        INSERT(d);
    }
#pragma unroll 4
    for (int s = 1; s < NPTS / 2; ++s) {
        const int jA = (j0 + s) & (NPTS - 1);
        const int jB = (j0 - s) & (NPTS - 1);
        const float4 qA = ps[jA];
        const float4 qB = ps[jB];
        const float dA = DIST(qA);
        const float dB = DIST(qB);
        INSERT(dA);
        INSERT(dB);
    }
    { // s = NPTS/2 (only one side: -1024 ≡ +1024 mod 2048)
        const int jC = (j0 + NPTS / 2) & (NPTS - 1);
        const float4 q = ps[jC];
        const float d = DIST(q);
        INSERT(d);
    }

    float s16 = 0.0f;
#pragma unroll
    for (int k = 0; k < KNN; k++) s16 += r[k];

#pragma unroll
    for (int off = 16; off > 0; off >>= 1)
        s16 += __shfl_down_sync(0xffffffffu, s16, off);

    if (lane == 0)
        g_partials[(c * BATCH + b) * TILES + tile] = s16;
}

// ---------------- finish: parallel reduce + MSE in double ----------------
__global__ __launch_bounds__(1024)
void finish_kernel(float* __restrict__ out) {
    __shared__ float ws[32];
    const int tid = threadIdx.x;

    float v = g_partials[tid];   // 1024 partials, warp w covers tiles of group w/2
#pragma unroll
    for (int off = 16; off > 0; off >>= 1)
        v += __shfl_down_sync(0xffffffffu, v, off);
    if ((tid & 31) == 0) ws[tid >> 5] = v;
    __syncthreads();

    if (tid == 0) {
        const double norm = 1.0 / ((double)NPTS * (double)KNN);
        double loss = 0.0;
        for (int g = 0; g < BATCH; ++g) {
            const double s0 = (double)ws[2 * g]             + (double)ws[2 * g + 1];
            const double s1 = (double)ws[2 * (BATCH + g)]   + (double)ws[2 * (BATCH + g) + 1];
            const double diff = (s0 - s1) * norm;
            loss += diff * diff;
        }
        out[0] = (float)(loss / (double)BATCH);
    }
}

extern "C" void kernel_launch(void* const* d_in, const int* in_sizes, int n_in,
                              void* d_out, int out_size) {
    const float* seed = (const float*)d_in[0];
    const float* gts  = (const float*)d_in[1];
    float* out = (float*)d_out;

    dim3 gsort(BATCH, 2);
    sort_kernel<<<gsort, 1024>>>(seed, gts);

    dim3 gknn(TILES, BATCH, 2);
    knn_kernel<<<gknn, TPB>>>();

    finish_kernel<<<1, 1024>>>(out);
}

// round 4
// speedup vs baseline: 1.4817x; 1.4817x over previous
#include <cuda_runtime.h>

#define BATCH 8
#define NPTS  2048
#define KNN   16
#define TPB   128
#define TILES (NPTS / TPB)      // 16 query-tiles per (cloud,batch)
#define NCB   (2 * BATCH)       // 16 (cloud,batch) groups
#define NCELL 512               // 8x8x8 Morton cells

__device__ float4 g_sorted[NCB * NPTS];            // 512 KB, cell-ordered points
__device__ float  g_partials[NCB * TILES];         // 256 block partials

// ---------------- spread 3 bits for 9-bit Morton ----------------
__device__ __forceinline__ int spread3(int v) {
    return (v & 1) | ((v & 2) << 2) | ((v & 4) << 4);
}

// ---------------- counting sort by Morton cell: one block per (c,b) ----------------
__global__ __launch_bounds__(256)
void cellsort_kernel(const float* __restrict__ seed, const float* __restrict__ gts) {
    __shared__ int hist[NCELL];
    __shared__ int wsum[8];
    __shared__ unsigned short cellOf[NPTS];

    const int b = blockIdx.x, c = blockIdx.y;
    const int tid = threadIdx.x;
    const int lane = tid & 31, wid = tid >> 5;
    const float* __restrict__ src = (c == 0 ? seed : gts) + (size_t)b * NPTS * 3;

    for (int i = tid; i < NCELL; i += 256) hist[i] = 0;
    __syncthreads();

    // histogram
    for (int p = tid; p < NPTS; p += 256) {
        const float x = src[3*p+0], y = src[3*p+1], z = src[3*p+2];
        int bx = (int)floorf((x + 3.0f) * (8.0f / 6.0f));
        int by = (int)floorf((y + 3.0f) * (8.0f / 6.0f));
        int bz = (int)floorf((z + 3.0f) * (8.0f / 6.0f));
        bx = min(max(bx, 0), 7); by = min(max(by, 0), 7); bz = min(max(bz, 0), 7);
        const int cell = spread3(bx) | (spread3(by) << 1) | (spread3(bz) << 2);
        cellOf[p] = (unsigned short)cell;
        atomicAdd(&hist[cell], 1);
    }
    __syncthreads();

    // exclusive prefix over 512 bins (each thread owns 2 bins)
    const int a0 = hist[2*tid], a1 = hist[2*tid+1];
    int s = a0 + a1;
#pragma unroll
    for (int off = 1; off < 32; off <<= 1) {
        const int n = __shfl_up_sync(0xffffffffu, s, off);
        if (lane >= off) s += n;
    }
    if (lane == 31) wsum[wid] = s;
    __syncthreads();
    if (tid < 8) {
        int w = wsum[tid];
#pragma unroll
        for (int off = 1; off < 8; off <<= 1) {
            const int n = __shfl_up_sync(0xffu, w, off);
            if ((int)tid >= off) w += n;
        }
        wsum[tid] = w;
    }
    __syncthreads();
    const int excl = (wid ? wsum[wid-1] : 0) + s - (a0 + a1);
    __syncthreads();                 // all bin reads done before overwrite
    hist[2*tid]   = excl;
    hist[2*tid+1] = excl + a0;
    __syncthreads();

    // scatter (within-cell order by atomic ticket; totals are permutation-invariant)
    float4* __restrict__ dst = g_sorted + (c * BATCH + b) * NPTS;
    for (int p = tid; p < NPTS; p += 256) {
        const float x = src[3*p+0], y = src[3*p+1], z = src[3*p+2]; // L1-hot
        const int pos = atomicAdd(&hist[cellOf[p]], 1);
        dst[pos] = make_float4(x, y, z, 0.0f);
    }
}

// ---------------- knn: lanes = 32 cell-adjacent queries, scan all 2048 ----------------
#define DIST(q) fmaf((q).x - pi.x, (q).x - pi.x,                          \
                fmaf((q).y - pi.y, (q).y - pi.y,                          \
                     ((q).z - pi.z) * ((q).z - pi.z)))

// depth-2 parallel sorted-ascending insert
#define INSERT(dv) do {                                                   \
    if ((dv) < r[KNN-1]) {                                                \
        _Pragma("unroll")                                                 \
        for (int k = KNN-1; k >= 1; --k)                                  \
            r[k] = fminf(r[k], fmaxf(r[k-1], (dv)));                      \
        r[0] = fminf(r[0], (dv));                                         \
    } } while (0)

__global__ __launch_bounds__(TPB)
void knn_kernel() {
    __shared__ float4 sp[NPTS];          // 32 KB
    __shared__ float red[TPB / 32];

    const int tile = blockIdx.x, b = blockIdx.y, c = blockIdx.z;
    const int tid = threadIdx.x;
    const float4* __restrict__ ps = g_sorted + (c * BATCH + b) * NPTS;

    for (int j = tid; j < NPTS; j += TPB) sp[j] = ps[j];   // coalesced LDG.128
    __syncthreads();

    const float4 pi = sp[tile * TPB + tid];

    float r[KNN];
#pragma unroll
    for (int k = 0; k < KNN; k++) r[k] = 3.0e38f;

#pragma unroll 4
    for (int j = 0; j < NPTS; j++) {
        const float4 q = sp[j];          // broadcast LDS.128
        const float d = DIST(q);
        INSERT(d);
    }

    float s16 = 0.0f;
#pragma unroll
    for (int k = 0; k < KNN; k++) s16 += r[k];

#pragma unroll
    for (int off = 16; off > 0; off >>= 1)
        s16 += __shfl_down_sync(0xffffffffu, s16, off);
    if ((tid & 31) == 0) red[tid >> 5] = s16;
    __syncthreads();
    if (tid == 0) {
        float bs = 0.0f;
#pragma unroll
        for (int w = 0; w < TPB / 32; w++) bs += red[w];
        g_partials[(c * BATCH + b) * TILES + tile] = bs;
    }
}

// ---------------- finish: 256 partials -> loss, parallel ----------------
__global__ __launch_bounds__(256)
void finish_kernel(float* __restrict__ out) {
    __shared__ float ws[NCB];
    const int tid = threadIdx.x;

    float v = g_partials[tid];           // group g = tid>>4 (16 partials each)
#pragma unroll
    for (int off = 8; off > 0; off >>= 1)
        v += __shfl_down_sync(0xffffffffu, v, off, 16);
    if ((tid & 15) == 0) ws[tid >> 4] = v;
    __syncthreads();

    if (tid == 0) {
        const double norm = 1.0 / ((double)NPTS * (double)KNN);
        double loss = 0.0;
        for (int g = 0; g < BATCH; ++g) {
            const double diff = ((double)ws[g] - (double)ws[BATCH + g]) * norm;
            loss += diff * diff;
        }
        out[0] = (float)(loss / (double)BATCH);
    }
}

extern "C" void kernel_launch(void* const* d_in, const int* in_sizes, int n_in,
                              void* d_out, int out_size) {
    const float* seed = (const float*)d_in[0];
    const float* gts  = (const float*)d_in[1];
    float* out = (float*)d_out;

    dim3 gsort(BATCH, 2);
    cellsort_kernel<<<gsort, 256>>>(seed, gts);

    dim3 gknn(TILES, BATCH, 2);
    knn_kernel<<<gknn, TPB>>>();

    finish_kernel<<<1, 256>>>(out);
}

// round 6
// speedup vs baseline: 2.5766x; 1.7390x over previous
#include <cuda_runtime.h>

#define BATCH 8
#define NPTS  2048
#define KNN   16
#define TPB   128
#define TILES (NPTS / TPB)      // 16 query-tiles per (cloud,batch)
#define NCB   (2 * BATCH)       // 16 (cloud,batch) groups
#define NCELL 512               // 8x8x8 Morton cells
#define NPAIR (NPTS / 2)        // 1024 point-pairs

// Cell-ordered SoA pairs: (x_{2j},x_{2j+1}) etc, per (cloud,batch) group.
__device__ unsigned long long g_sx[NCB * NPAIR];
__device__ unsigned long long g_sy[NCB * NPAIR];
__device__ unsigned long long g_sz[NCB * NPAIR];
__device__ float g_partials[NCB * TILES];

// ---------------- f32x2 packed helpers (FFMA2/FADD2/FMUL2, PTX-only) ----------------
__device__ __forceinline__ unsigned long long x2add(unsigned long long a, unsigned long long b) {
    unsigned long long r; asm("add.rn.f32x2 %0, %1, %2;" : "=l"(r) : "l"(a), "l"(b)); return r;
}
__device__ __forceinline__ unsigned long long x2mul(unsigned long long a, unsigned long long b) {
    unsigned long long r; asm("mul.rn.f32x2 %0, %1, %2;" : "=l"(r) : "l"(a), "l"(b)); return r;
}
__device__ __forceinline__ unsigned long long x2fma(unsigned long long a, unsigned long long b,
                                                    unsigned long long c) {
    unsigned long long r; asm("fma.rn.f32x2 %0, %1, %2, %3;" : "=l"(r) : "l"(a), "l"(b), "l"(c)); return r;
}
__device__ __forceinline__ unsigned long long x2pack(float lo, float hi) {
    unsigned long long r; asm("mov.b64 %0, {%1, %2};" : "=l"(r) : "f"(lo), "f"(hi)); return r;
}
__device__ __forceinline__ void x2unpack(float& lo, float& hi, unsigned long long v) {
    asm("mov.b64 {%0, %1}, %2;" : "=f"(lo), "=f"(hi) : "l"(v));
}

__device__ __forceinline__ int spread3(int v) {
    return (v & 1) | ((v & 2) << 2) | ((v & 4) << 4);
}

// ---------------- counting sort by Morton cell: one 512-thread block per (c,b) ----------------
__global__ __launch_bounds__(512)
void cellsort_kernel(const float* __restrict__ seed, const float* __restrict__ gts) {
    __shared__ int hist[NCELL];
    __shared__ int wsum[16];
    __shared__ unsigned short cellOf[NPTS];

    const int b = blockIdx.x, c = blockIdx.y;
    const int tid = threadIdx.x;
    const int lane = tid & 31, wid = tid >> 5;
    const float* __restrict__ src = (c == 0 ? seed : gts) + (size_t)b * NPTS * 3;

    hist[tid] = 0;
    __syncthreads();

    for (int p = tid; p < NPTS; p += 512) {
        const float x = src[3*p+0], y = src[3*p+1], z = src[3*p+2];
        int bx = (int)floorf((x + 3.0f) * (8.0f / 6.0f));
        int by = (int)floorf((y + 3.0f) * (8.0f / 6.0f));
        int bz = (int)floorf((z + 3.0f) * (8.0f / 6.0f));
        bx = min(max(bx, 0), 7); by = min(max(by, 0), 7); bz = min(max(bz, 0), 7);
        const int cell = spread3(bx) | (spread3(by) << 1) | (spread3(bz) << 2);
        cellOf[p] = (unsigned short)cell;
        atomicAdd(&hist[cell], 1);
    }
    __syncthreads();

    // exclusive prefix over 512 bins (1 bin per thread)
    const int a = hist[tid];
    int s = a;
#pragma unroll
    for (int off = 1; off < 32; off <<= 1) {
        const int n = __shfl_up_sync(0xffffffffu, s, off);
        if (lane >= off) s += n;
    }
    if (lane == 31) wsum[wid] = s;
    __syncthreads();
    if (tid < 16) {
        int w = wsum[tid];
#pragma unroll
        for (int off = 1; off < 16; off <<= 1) {
            const int n = __shfl_up_sync(0xffffu, w, off, 16);
            if (tid >= off) w += n;
        }
        wsum[tid] = w;
    }
    __syncthreads();
    const int excl = (wid ? wsum[wid - 1] : 0) + s - a;
    hist[tid] = excl;               // each thread touches only its own bin
    __syncthreads();

    // scatter into SoA pair layout (within-cell order arbitrary; sums invariant)
    float* __restrict__ dx = (float*)(g_sx + (c * BATCH + b) * NPAIR);
    float* __restrict__ dy = (float*)(g_sy + (c * BATCH + b) * NPAIR);
    float* __restrict__ dz = (float*)(g_sz + (c * BATCH + b) * NPAIR);
    for (int p = tid; p < NPTS; p += 512) {
        const float x = src[3*p+0], y = src[3*p+1], z = src[3*p+2];   // L1-hot
        const int pos = atomicAdd(&hist[cellOf[p]], 1);
        dx[pos] = x; dy[pos] = y; dz[pos] = z;
    }
}

// depth-2 parallel sorted-ascending insert (unconditional; no-op if dv >= r[15])
#define INS(dv) do {                                                      \
    _Pragma("unroll")                                                     \
    for (int k = KNN - 1; k >= 1; --k)                                    \
        r[k] = fminf(r[k], fmaxf(r[k-1], (dv)));                          \
    r[0] = fminf(r[0], (dv));                                             \
} while (0)

#define PAIR_BODY(jp) do {                                                \
    const unsigned long long X = sx[jp], Y = sy[jp], Z = sz[jp];          \
    const unsigned long long ddx = x2add(X, npx);                         \
    const unsigned long long ddy = x2add(Y, npy);                         \
    const unsigned long long ddz = x2add(Z, npz);                         \
    const unsigned long long d2 =                                         \
        x2fma(ddx, ddx, x2fma(ddy, ddy, x2mul(ddz, ddz)));                \
    float dA, dB; x2unpack(dA, dB, d2);                                   \
    if (fminf(dA, dB) < r[KNN-1]) { INS(dA); INS(dB); }                   \
} while (0)

// ---------------- knn: scan starts at the query tile (warm threshold fast) ----------------
__global__ __launch_bounds__(TPB)
void knn_kernel() {
    __shared__ unsigned long long sx[NPAIR];   // 8 KB each
    __shared__ unsigned long long sy[NPAIR];
    __shared__ unsigned long long sz[NPAIR];
    __shared__ float red[TPB / 32];

    const int tile = blockIdx.x, b = blockIdx.y, c = blockIdx.z;
    const int tid = threadIdx.x;
    const int g = (c * BATCH + b) * NPAIR;

    for (int j = tid; j < NPAIR; j += TPB) {
        sx[j] = g_sx[g + j];
        sy[j] = g_sy[g + j];
        sz[j] = g_sz[g + j];
    }
    __syncthreads();

    // query point: position tile*TPB + tid in sorted order
    const int p = tile * TPB + tid;
    float qx, qy, qz, hx, hy, hz;
    x2unpack(qx, hx, sx[p >> 1]);
    x2unpack(qy, hy, sy[p >> 1]);
    x2unpack(qz, hz, sz[p >> 1]);
    if (p & 1) { qx = hx; qy = hy; qz = hz; }
    const unsigned long long npx = x2pack(-qx, -qx);
    const unsigned long long npy = x2pack(-qy, -qy);
    const unsigned long long npz = x2pack(-qz, -qz);

    float r[KNN];
#pragma unroll
    for (int k = 0; k < KNN; k++) r[k] = 3.0e38f;

    const int sp0 = tile * (TPB / 2);    // block-uniform pair index of own tile
#pragma unroll 4
    for (int jp = sp0; jp < NPAIR; ++jp) PAIR_BODY(jp);
#pragma unroll 4
    for (int jp = 0; jp < sp0; ++jp) PAIR_BODY(jp);

    float s16 = 0.0f;
#pragma unroll
    for (int k = 0; k < KNN; k++) s16 += r[k];

#pragma unroll
    for (int off = 16; off > 0; off >>= 1)
        s16 += __shfl_down_sync(0xffffffffu, s16, off);
    if ((tid & 31) == 0) red[tid >> 5] = s16;
    __syncthreads();
    if (tid == 0) {
        float bs = 0.0f;
#pragma unroll
        for (int w = 0; w < TPB / 32; w++) bs += red[w];
        g_partials[(c * BATCH + b) * TILES + tile] = bs;
    }
}

// ---------------- finish ----------------
__global__ __launch_bounds__(256)
void finish_kernel(float* __restrict__ out) {
    __shared__ float ws[NCB];
    const int tid = threadIdx.x;

    float v = g_partials[tid];
#pragma unroll
    for (int off = 8; off > 0; off >>= 1)
        v += __shfl_down_sync(0xffffffffu, v, off, 16);
    if ((tid & 15) == 0) ws[tid >> 4] = v;
    __syncthreads();

    if (tid == 0) {
        const double norm = 1.0 / ((double)NPTS * (double)KNN);
        double loss = 0.0;
        for (int g = 0; g < BATCH; ++g) {
            const double diff = ((double)ws[g] - (double)ws[BATCH + g]) * norm;
            loss += diff * diff;
        }
        out[0] = (float)(loss / (double)BATCH);
    }
}

extern "C" void kernel_launch(void* const* d_in, const int* in_sizes, int n_in,
                              void* d_out, int out_size) {
    const float* seed = (const float*)d_in[0];
    const float* gts  = (const float*)d_in[1];
    float* out = (float*)d_out;

    dim3 gsort(BATCH, 2);
    cellsort_kernel<<<gsort, 512>>>(seed, gts);

    dim3 gknn(TILES, BATCH, 2);
    knn_kernel<<<gknn, TPB>>>();

    finish_kernel<<<1, 256>>>(out);
}